// round 8
// baseline (speedup 1.0000x reference)
#include <cuda_runtime.h>
#include <math.h>

#define BB 2
#define CC 32
#define EE 128
#define SS 64
#define VV (SS*SS*SS)       /* 262144 = 2^18 */
#define KV 343

typedef unsigned long long ull;

/* ---- scratch (static __device__: allocation-free per harness rules) ---- */
__device__ float g_y[(size_t)BB*CC*VV];   /* depthwise-conv output (valid at active voxels only) */
__device__ int   g_list[BB*VV];           /* compacted active voxel ids: id = b*V + v */
__device__ int   g_cnt;

/* ---------------- K0: reset counter ---------------- */
__global__ void k0_reset() { if (threadIdx.x == 0) g_cnt = 0; }

/* ---------------- K1: xm = x*m -> out (residual base), build active list -------- */
__global__ __launch_bounds__(256) void k1_mask_pack(
    const float* __restrict__ x, const int* __restrict__ mask,
    float* __restrict__ out)
{
    int i = blockIdx.x * blockDim.x + threadIdx.x;   /* i in [0, B*V), exact grid */
    int b = i >> 18;
    int v = i & (VV - 1);
    int m = mask[i];
    float fm = (float)m;
    const float* xb = x   + (size_t)b * CC * VV + v;
    float*       ob = out + (size_t)b * CC * VV + v;
#pragma unroll
    for (int c = 0; c < CC; c++)
        ob[(size_t)c * VV] = xb[(size_t)c * VV] * fm;

    /* warp-aggregated compaction push */
    unsigned act = __ballot_sync(0xffffffffu, m != 0);
    if (act) {
        int lane   = threadIdx.x & 31;
        int leader = __ffs(act) - 1;
        int base = 0;
        if (lane == leader) base = atomicAdd(&g_cnt, __popc(act));
        base = __shfl_sync(0xffffffffu, base, leader);
        if (m) g_list[base + __popc(act & ((1u << lane) - 1u))] = i;
    }
}

/* ---------------- K2: depthwise 7x7x7 conv, f32x2 (FFMA2), static smem ---------
 * Outputs per block: 32(x) x 4(y) x 8(z). 64 threads = 16 x-pairs * 4 y.
 * Each thread computes an x-PAIR of outputs over 8 z via a 14-deep sliding
 * window: every window load is an aligned LDS.64 (f32x2). Odd-dx taps read a
 * second smem copy shifted one float in x, so pair loads stay 8B-aligned.
 * Weights pre-duplicated (w,w) -> broadcast LDS.64.
 * All accumulation via fma.rn.f32x2 -> FFMA2 (2 FMA per issue slot).
 * Static smem total 47544 B (< 48KB): no attribute call, no dynamic smem.
 */
#define K2_TZ 8
#define K2_TY 4
#define K2_XW 38          /* input x extent (32 + 6 halo) */
#define K2_XP 40          /* padded (even) x stride */
#define K2_YW 10          /* input y extent (4 + 6)  */
#define K2_ZW 14          /* input z extent (8 + 6) */
#define K2_TILE (K2_ZW * K2_YW * K2_XP)   /* 5600 floats */

__device__ __forceinline__ ull ffma2(ull a, ull b, ull c) {
    ull d;
    asm("fma.rn.f32x2 %0, %1, %2, %3;" : "=l"(d) : "l"(a), "l"(b), "l"(c));
    return d;
}

__global__ __launch_bounds__(64) void k2_dwconv(
    const float* __restrict__ xm,        /* = out buffer (holds x*m) */
    const int*   __restrict__ mask,
    const float* __restrict__ w_dw,
    const float* __restrict__ b_dw)
{
    __shared__ __align__(16) float  s_a[K2_TILE];   /* tile copy A */
    __shared__ __align__(16) float  s_b[K2_TILE];   /* tile copy B = A shifted 1 in x */
    __shared__ __align__(16) float2 wdup[KV];

    int c = blockIdx.y, b = blockIdx.z;
    int t  = blockIdx.x;               /* 256 tiles: 2x * 16y * 8z */
    int xt = t & 1;
    int yt = (t >> 1) & 15;
    int zt = t >> 5;
    int x0 = xt * 32, y0 = yt * K2_TY, z0 = zt * K2_TZ;
    int tid = threadIdx.x;

    /* duplicated weights */
    const float* wsrc = w_dw + c * KV;
    for (int j = tid; j < KV; j += 64) {
        float w = wsrc[j];
        wdup[j] = make_float2(w, w);
    }

    /* tile load: 14 x 10 x 38 = 5320 elements, write both copies */
    const float* src = xm + (size_t)(b * CC + c) * VV;
    for (int j = tid; j < K2_ZW * K2_YW * K2_XW; j += 64) {
        int lz = j / (K2_YW * K2_XW);
        int r  = j - lz * (K2_YW * K2_XW);
        int ly = r / K2_XW;
        int lx = r - ly * K2_XW;
        int gz = z0 - 3 + lz, gy = y0 - 3 + ly, gx = x0 - 3 + lx;
        float val = 0.f;
        if (((unsigned)gz < SS) & ((unsigned)gy < SS) & ((unsigned)gx < SS))
            val = src[gz * 4096 + gy * 64 + gx];
        int o = (lz * K2_YW + ly) * K2_XP + lx;
        s_a[o] = val;
        if (lx) s_b[o - 1] = val;
    }
    __syncthreads();

    int xp = tid & 15;          /* x-pair index: outputs x0+2*xp, x0+2*xp+1 */
    int ty = tid >> 4;          /* y row 0..3 */

    ull acc2[K2_TZ];
#pragma unroll
    for (int k = 0; k < K2_TZ; k++) acc2[k] = 0ULL;

#pragma unroll 1
    for (int dy = 0; dy < 7; dy++) {
#pragma unroll 1
        for (int dx = 0; dx < 7; dx++) {
            const float* cp = (dx & 1) ? s_b : s_a;
            int xoff = 2 * xp + (dx & ~1);
            const float* col = cp + (ty + dy) * K2_XP + xoff;
            ull win2[K2_ZW];
#pragma unroll
            for (int j = 0; j < K2_ZW; j++)
                win2[j] = *(const ull*)(col + j * (K2_YW * K2_XP));
#pragma unroll
            for (int dz = 0; dz < 7; dz++) {
                ull wv = *(const ull*)&wdup[(dz * 7 + dy) * 7 + dx];
#pragma unroll
                for (int k = 0; k < K2_TZ; k++)
                    acc2[k] = ffma2(wv, win2[k + dz], acc2[k]);
            }
        }
    }

    float bd = b_dw[c];
    int gx = x0 + 2 * xp, gy = y0 + ty;
    const int* mk  = mask + b * VV;
    float*     dst = g_y + (size_t)(b * CC + c) * VV;
#pragma unroll
    for (int k = 0; k < K2_TZ; k++) {
        int v = (z0 + k) * 4096 + gy * 64 + gx;
        int2 mm = *(const int2*)(mk + v);            /* gx even -> 8B aligned */
        float lo = __uint_as_float((unsigned)acc2[k]);
        float hi = __uint_as_float((unsigned)(acc2[k] >> 32));
        if (mm.x) dst[v]     = lo + bd;
        if (mm.y) dst[v + 1] = hi + bd;
    }
}

/* ---------------- K3: LN + expand/GELU + project + residual add ----------------
 * One thread = ONE active voxel (low regs -> decent occupancy).
 * Weights in smem, broadcast float4 reads.
 */
__device__ __forceinline__ float gelu_f(float x) {
    return 0.5f * x * (1.f + erff(x * 0.70710678118654752440f));
}

__global__ __launch_bounds__(128, 4) void k3_mlp(
    const float* __restrict__ ln_g, const float* __restrict__ ln_b,
    const float* __restrict__ w2,   const float* __restrict__ b2,
    const float* __restrict__ w3,   const float* __restrict__ b3,
    float* __restrict__ out)
{
    int n = g_cnt;
    int blk0 = blockIdx.x * 128;
    if (blk0 >= n) return;

    __shared__ __align__(16) float w2s[EE * CC];
    __shared__ __align__(16) float w3s[CC * EE];
    __shared__ float b2s[EE];
    __shared__ float prm[3 * CC];   /* ln_g | ln_b | b3 */

    int tid = threadIdx.x;
    for (int j = tid; j < EE * CC; j += 128) { w2s[j] = w2[j]; w3s[j] = w3[j]; }
    b2s[tid] = b2[tid];
    if (tid < CC) { prm[tid] = ln_g[tid]; prm[CC + tid] = ln_b[tid]; prm[2 * CC + tid] = b3[tid]; }
    __syncthreads();

    int  slot = blk0 + tid;
    bool ok   = slot < n;
    int  id   = g_list[ok ? slot : blk0];
    int  bI   = id >> 18, vI = id & (VV - 1);

    float yv[CC];
    const float* yp = g_y + (size_t)bI * CC * VV + vI;
#pragma unroll
    for (int c = 0; c < CC; c++) yv[c] = yp[(size_t)c * VV];

    /* per-voxel LayerNorm over channels (thread-local) */
    float s = 0.f;
#pragma unroll
    for (int c = 0; c < CC; c++) s += yv[c];
    float mu = s * (1.f / CC);
    float vs = 0.f;
#pragma unroll
    for (int c = 0; c < CC; c++) { float d = yv[c] - mu; vs = fmaf(d, d, vs); }
    float rs = rsqrtf(vs * (1.f / CC) + 1e-6f);
#pragma unroll
    for (int c = 0; c < CC; c++)
        yv[c] = fmaf((yv[c] - mu) * rs, prm[c], prm[CC + c]);

    float o[CC];
#pragma unroll
    for (int c = 0; c < CC; c++) o[c] = prm[2 * CC + c];

    const float4* w2v = (const float4*)w2s;
    const float4* w3v = (const float4*)w3s;

#pragma unroll 1
    for (int ec = 0; ec < EE; ec += 8) {
        float h[8];
#pragma unroll
        for (int j = 0; j < 8; j++) {
            float z = b2s[ec + j];
#pragma unroll
            for (int q = 0; q < CC / 4; q++) {
                float4 w = w2v[(ec + j) * (CC / 4) + q];
                z = fmaf(yv[4*q+0], w.x, z);
                z = fmaf(yv[4*q+1], w.y, z);
                z = fmaf(yv[4*q+2], w.z, z);
                z = fmaf(yv[4*q+3], w.w, z);
            }
            h[j] = gelu_f(z);
        }
#pragma unroll
        for (int cc2 = 0; cc2 < CC; cc2++) {
            float4 a  = w3v[cc2 * (EE / 4) + (ec >> 2)];
            float4 bq = w3v[cc2 * (EE / 4) + (ec >> 2) + 1];
            float acc = o[cc2];
            acc = fmaf(h[0], a.x,  acc);
            acc = fmaf(h[1], a.y,  acc);
            acc = fmaf(h[2], a.z,  acc);
            acc = fmaf(h[3], a.w,  acc);
            acc = fmaf(h[4], bq.x, acc);
            acc = fmaf(h[5], bq.y, acc);
            acc = fmaf(h[6], bq.z, acc);
            acc = fmaf(h[7], bq.w, acc);
            o[cc2] = acc;
        }
    }

    if (ok) {
        float* op = out + (size_t)bI * CC * VV + vI;
#pragma unroll
        for (int c = 0; c < CC; c++)
            op[(size_t)c * VV] += o[c];      /* out held xm -> xm + o */
    }
}

/* ---------------- launcher ---------------- */
extern "C" void kernel_launch(void* const* d_in, const int* in_sizes, int n_in,
                              void* d_out, int out_size)
{
    const float* x    = (const float*)d_in[0];
    const int*   mask = (const int*)  d_in[1];
    const float* w_dw = (const float*)d_in[2];
    const float* b_dw = (const float*)d_in[3];
    const float* ln_g = (const float*)d_in[4];
    const float* ln_b = (const float*)d_in[5];
    const float* w2   = (const float*)d_in[6];
    const float* b2   = (const float*)d_in[7];
    const float* w3   = (const float*)d_in[8];
    const float* b3   = (const float*)d_in[9];
    float* out = (float*)d_out;

    k0_reset<<<1, 32>>>();
    k1_mask_pack<<<(BB * VV) / 256, 256>>>(x, mask, out);
    dim3 g2(256, CC, BB);
    k2_dwconv<<<g2, 64>>>(out, mask, w_dw, b_dw);
    k3_mlp<<<(BB * VV) / 128, 128>>>(ln_g, ln_b, w2, b2, w3, b3, out);
}

// round 9
// speedup vs baseline: 1.4976x; 1.4976x over previous
#include <cuda_runtime.h>
#include <math.h>

#define BB 2
#define CC 32
#define EE 128
#define SS 64
#define VV (SS*SS*SS)       /* 262144 = 2^18 */
#define KV 343

typedef unsigned long long ull;

/* ---- scratch (static __device__: allocation-free per harness rules) ---- */
__device__ float g_y[(size_t)BB*CC*VV];   /* depthwise-conv output (valid at active voxels only) */
__device__ int   g_list[BB*VV];           /* compacted active voxel ids: id = b*V + v */
__device__ int   g_cnt;

/* ---------------- K0: reset counter ---------------- */
__global__ void k0_reset() { if (threadIdx.x == 0) g_cnt = 0; }

/* ---------------- K1: xm = x*m -> out (residual base), build active list --------
 * Vectorized: one thread handles 4 consecutive voxels (float4/int4). */
__global__ __launch_bounds__(256) void k1_mask_pack(
    const float* __restrict__ x, const int* __restrict__ mask,
    float* __restrict__ out)
{
    int t  = blockIdx.x * blockDim.x + threadIdx.x;   /* t in [0, B*V/4) */
    int i0 = t * 4;
    int b  = i0 >> 18;
    int v  = i0 & (VV - 1);
    int4 m4 = *(const int4*)(mask + i0);
    float4 f4 = make_float4((float)m4.x, (float)m4.y, (float)m4.z, (float)m4.w);
    const float* xb = x   + (size_t)b * CC * VV + v;
    float*       ob = out + (size_t)b * CC * VV + v;
#pragma unroll
    for (int c = 0; c < CC; c++) {
        float4 xv = *(const float4*)(xb + (size_t)c * VV);
        xv.x *= f4.x; xv.y *= f4.y; xv.z *= f4.z; xv.w *= f4.w;
        *(float4*)(ob + (size_t)c * VV) = xv;
    }
    int mm[4] = { m4.x, m4.y, m4.z, m4.w };
#pragma unroll
    for (int p = 0; p < 4; p++) {
        unsigned act = __ballot_sync(0xffffffffu, mm[p] != 0);
        if (act) {
            int lane   = threadIdx.x & 31;
            int leader = __ffs(act) - 1;
            int base = 0;
            if (lane == leader) base = atomicAdd(&g_cnt, __popc(act));
            base = __shfl_sync(0xffffffffu, base, leader);
            if (mm[p]) g_list[base + __popc(act & ((1u << lane) - 1u))] = i0 + p;
        }
    }
}

/* ---------------- K2: depthwise 7x7x7 conv, f32x2, SINGLE-copy smem ------------
 * Block outputs: 32(x) x 8(y) x 8(z). 128 threads = 16 x-pairs * 8 y rows,
 * each thread: one x-PAIR over 8 z (14-deep z window, value-centric FMA).
 * Even-dx taps: aligned LDS.64 pair loads. Odd-dx taps: pair built from the
 * RETAINED hi-half of the previous even window + current window's lo-half
 * (mov.b64) -- no second smem copy needed.
 * Tile: 14z x 14y x 40x(pad) = 31360B + 2744B weights = 34.1KB static
 *  -> 128-thr blocks, 4-5 blocks/SM (16-20 warps/SM) vs R7's 8 warps.
 */
#define K2_XP 40
#define K2_YW 14
#define K2_ZW 14
#define K2_XW 38
#define K2_TILE (K2_ZW * K2_YW * K2_XP)   /* 7840 floats */

__device__ __forceinline__ ull ffma2(ull a, ull b, ull c) {
    ull d;
    asm("fma.rn.f32x2 %0, %1, %2, %3;" : "=l"(d) : "l"(a), "l"(b), "l"(c));
    return d;
}
__device__ __forceinline__ ull pack2(float lo, float hi) {
    ull r;
    asm("mov.b64 %0, {%1, %2};" : "=l"(r) : "f"(lo), "f"(hi));
    return r;
}

__global__ __launch_bounds__(128) void k2_dwconv(
    const float* __restrict__ xm,        /* = out buffer (holds x*m) */
    const int*   __restrict__ mask,
    const float* __restrict__ w_dw,
    const float* __restrict__ b_dw)
{
    __shared__ __align__(16) float  s_in[K2_TILE];
    __shared__ __align__(16) float2 wdup[KV];

    int c = blockIdx.y, b = blockIdx.z;
    int t  = blockIdx.x;               /* 128 tiles: 2x * 8y * 8z */
    int xt = t & 1;
    int yt = (t >> 1) & 7;
    int zt = t >> 4;
    int x0 = xt * 32, y0 = yt * 8, z0 = zt * 8;
    int tid = threadIdx.x;

    /* duplicated weights (w,w) for f32x2 */
    const float* wsrc = w_dw + c * KV;
    for (int j = tid; j < KV; j += 128) {
        float w = wsrc[j];
        wdup[j] = make_float2(w, w);
    }

    /* tile load: 14 x 14 x 38 = 7448 elements */
    const float* src = xm + (size_t)(b * CC + c) * VV;
    for (int j = tid; j < K2_ZW * K2_YW * K2_XW; j += 128) {
        int lz = j / (K2_YW * K2_XW);
        int r  = j - lz * (K2_YW * K2_XW);
        int ly = r / K2_XW;
        int lx = r - ly * K2_XW;
        int gz = z0 - 3 + lz, gy = y0 - 3 + ly, gx = x0 - 3 + lx;
        float val = 0.f;
        if (((unsigned)gz < SS) & ((unsigned)gy < SS) & ((unsigned)gx < SS))
            val = src[gz * 4096 + gy * 64 + gx];
        s_in[(lz * K2_YW + ly) * K2_XP + lx] = val;
    }
    __syncthreads();

    int xp = tid & 15;          /* x-pair: outputs x0+2*xp, x0+2*xp+1 */
    int ty = tid >> 4;          /* y row 0..7 */

    ull acc[8];
#pragma unroll
    for (int k = 0; k < 8; k++) acc[k] = 0ULL;

#pragma unroll 1
    for (int dy = 0; dy < 7; dy++) {
        const float* row = s_in + (ty + dy) * K2_XP + 2 * xp;
        float hi[K2_ZW];

        /* ---- dx = 0 (even, aligned) ---- */
        {
            ull wz[7];
#pragma unroll
            for (int dz = 0; dz < 7; dz++)
                wz[dz] = *(const ull*)&wdup[(dz * 7 + dy) * 7 + 0];
#pragma unroll
            for (int j = 0; j < K2_ZW; j++) {
                float2 wv = *(const float2*)(row + j * (K2_YW * K2_XP));
                ull v = pack2(wv.x, wv.y);
#pragma unroll
                for (int dz = 0; dz < 7; dz++) {
                    int k = j - dz;
                    if (k >= 0 && k < 8) acc[k] = ffma2(wz[dz], v, acc[k]);
                }
                hi[j] = wv.y;
            }
        }

        /* ---- e = 2,4,6: odd pass (dx=e-1) fused with even pass (dx=e) ---- */
#pragma unroll
        for (int e = 2; e <= 6; e += 2) {
            ull wzo[7], wze[7];
#pragma unroll
            for (int dz = 0; dz < 7; dz++) {
                wzo[dz] = *(const ull*)&wdup[(dz * 7 + dy) * 7 + (e - 1)];
                wze[dz] = *(const ull*)&wdup[(dz * 7 + dy) * 7 + e];
            }
#pragma unroll
            for (int j = 0; j < K2_ZW; j++) {
                float2 wv = *(const float2*)(row + j * (K2_YW * K2_XP) + e);
                ull q = pack2(hi[j], wv.x);   /* odd-dx pair */
                ull v = pack2(wv.x, wv.y);    /* even-dx pair */
#pragma unroll
                for (int dz = 0; dz < 7; dz++) {
                    int k = j - dz;
                    if (k >= 0 && k < 8) {
                        acc[k] = ffma2(wzo[dz], q, acc[k]);
                        acc[k] = ffma2(wze[dz], v, acc[k]);
                    }
                }
                hi[j] = wv.y;
            }
        }
    }

    float bd = b_dw[c];
    int gx = x0 + 2 * xp, gy = y0 + ty;
    const int* mk  = mask + b * VV;
    float*     dst = g_y + (size_t)(b * CC + c) * VV;
#pragma unroll
    for (int k = 0; k < 8; k++) {
        int v = (z0 + k) * 4096 + gy * 64 + gx;
        int2 mm = *(const int2*)(mk + v);            /* gx even -> 8B aligned */
        float lo = __uint_as_float((unsigned)acc[k]);
        float hi2 = __uint_as_float((unsigned)(acc[k] >> 32));
        if (mm.x) dst[v]     = lo + bd;
        if (mm.y) dst[v + 1] = hi2 + bd;
    }
}

/* ---------------- K3: LN + expand/GELU + project + residual add ----------------
 * UNCHANGED from passing R7 version (114.8us, regs=128, occ 23%). */
__device__ __forceinline__ float gelu_f(float x) {
    return 0.5f * x * (1.f + erff(x * 0.70710678118654752440f));
}

__global__ __launch_bounds__(128, 4) void k3_mlp(
    const float* __restrict__ ln_g, const float* __restrict__ ln_b,
    const float* __restrict__ w2,   const float* __restrict__ b2,
    const float* __restrict__ w3,   const float* __restrict__ b3,
    float* __restrict__ out)
{
    int n = g_cnt;
    int blk0 = blockIdx.x * 128;
    if (blk0 >= n) return;

    __shared__ __align__(16) float w2s[EE * CC];
    __shared__ __align__(16) float w3s[CC * EE];
    __shared__ float b2s[EE];
    __shared__ float prm[3 * CC];   /* ln_g | ln_b | b3 */

    int tid = threadIdx.x;
    for (int j = tid; j < EE * CC; j += 128) { w2s[j] = w2[j]; w3s[j] = w3[j]; }
    b2s[tid] = b2[tid];
    if (tid < CC) { prm[tid] = ln_g[tid]; prm[CC + tid] = ln_b[tid]; prm[2 * CC + tid] = b3[tid]; }
    __syncthreads();

    int  slot = blk0 + tid;
    bool ok   = slot < n;
    int  id   = g_list[ok ? slot : blk0];
    int  bI   = id >> 18, vI = id & (VV - 1);

    float yv[CC];
    const float* yp = g_y + (size_t)bI * CC * VV + vI;
#pragma unroll
    for (int c = 0; c < CC; c++) yv[c] = yp[(size_t)c * VV];

    float s = 0.f;
#pragma unroll
    for (int c = 0; c < CC; c++) s += yv[c];
    float mu = s * (1.f / CC);
    float vs = 0.f;
#pragma unroll
    for (int c = 0; c < CC; c++) { float d = yv[c] - mu; vs = fmaf(d, d, vs); }
    float rs = rsqrtf(vs * (1.f / CC) + 1e-6f);
#pragma unroll
    for (int c = 0; c < CC; c++)
        yv[c] = fmaf((yv[c] - mu) * rs, prm[c], prm[CC + c]);

    float o[CC];
#pragma unroll
    for (int c = 0; c < CC; c++) o[c] = prm[2 * CC + c];

    const float4* w2v = (const float4*)w2s;
    const float4* w3v = (const float4*)w3s;

#pragma unroll 1
    for (int ec = 0; ec < EE; ec += 8) {
        float h[8];
#pragma unroll
        for (int j = 0; j < 8; j++) {
            float z = b2s[ec + j];
#pragma unroll
            for (int q = 0; q < CC / 4; q++) {
                float4 w = w2v[(ec + j) * (CC / 4) + q];
                z = fmaf(yv[4*q+0], w.x, z);
                z = fmaf(yv[4*q+1], w.y, z);
                z = fmaf(yv[4*q+2], w.z, z);
                z = fmaf(yv[4*q+3], w.w, z);
            }
            h[j] = gelu_f(z);
        }
#pragma unroll
        for (int cc2 = 0; cc2 < CC; cc2++) {
            float4 a  = w3v[cc2 * (EE / 4) + (ec >> 2)];
            float4 bq = w3v[cc2 * (EE / 4) + (ec >> 2) + 1];
            float acc = o[cc2];
            acc = fmaf(h[0], a.x,  acc);
            acc = fmaf(h[1], a.y,  acc);
            acc = fmaf(h[2], a.z,  acc);
            acc = fmaf(h[3], a.w,  acc);
            acc = fmaf(h[4], bq.x, acc);
            acc = fmaf(h[5], bq.y, acc);
            acc = fmaf(h[6], bq.z, acc);
            acc = fmaf(h[7], bq.w, acc);
            o[cc2] = acc;
        }
    }

    if (ok) {
        float* op = out + (size_t)bI * CC * VV + vI;
#pragma unroll
        for (int c = 0; c < CC; c++)
            op[(size_t)c * VV] += o[c];      /* out held xm -> xm + o */
    }
}

/* ---------------- launcher ---------------- */
extern "C" void kernel_launch(void* const* d_in, const int* in_sizes, int n_in,
                              void* d_out, int out_size)
{
    const float* x    = (const float*)d_in[0];
    const int*   mask = (const int*)  d_in[1];
    const float* w_dw = (const float*)d_in[2];
    const float* b_dw = (const float*)d_in[3];
    const float* ln_g = (const float*)d_in[4];
    const float* ln_b = (const float*)d_in[5];
    const float* w2   = (const float*)d_in[6];
    const float* b2   = (const float*)d_in[7];
    const float* w3   = (const float*)d_in[8];
    const float* b3   = (const float*)d_in[9];
    float* out = (float*)d_out;

    k0_reset<<<1, 32>>>();
    k1_mask_pack<<<(BB * VV / 4) / 256, 256>>>(x, mask, out);
    dim3 g2(128, CC, BB);
    k2_dwconv<<<g2, 128>>>(out, mask, w_dw, b_dw);
    k3_mlp<<<(BB * VV) / 128, 128>>>(ln_g, ln_b, w2, b2, w3, b3, out);
}